// round 2
// baseline (speedup 1.0000x reference)
#include <cuda_runtime.h>
#include <math.h>

// Problem constants
#define BATCH 4
#define SEQ   1024
#define DM    1024
#define NH    16
#define DH    64
#define BHN   (BATCH*NH)   // 64 flattened (b,h) rows per query index i

// Scratch (device globals — no allocation allowed)
__device__ float g_q[(size_t)BATCH*NH*SEQ*DH];   // [b*NH+h][s][d]
__device__ float g_k[(size_t)BATCH*SEQ*DH];      // [b*S+s][d]
__device__ float g_v[(size_t)BATCH*SEQ*DH];
__device__ float g_ctx[(size_t)BATCH*SEQ*DM];    // [b*S+s][h*DH+d]

// ---------------------------------------------------------------------------
// Tiled SGEMM: C = A @ B^T (+bias), A[M,K] row-major, B[N,K] row-major.
// 128x128 tile, BK=8, 256 threads, 8x8 microtile.
// MODE 0: plain C[m*N+n]
// MODE 1: q permuted write into [b,h,s,d]
// MODE 2: + bias[n]
// ---------------------------------------------------------------------------
template<int MODE>
__global__ __launch_bounds__(256)
void gemm_tn(const float* __restrict__ A, const float* __restrict__ B,
             const float* __restrict__ bias, float* __restrict__ C,
             int M, int N, int K)
{
    __shared__ float As[8][128];
    __shared__ float Bs[8][128];

    const int tid = threadIdx.x;
    const int tx = tid & 15;        // 16 col groups
    const int ty = tid >> 4;        // 16 row groups
    const int m0 = blockIdx.y * 128;
    const int n0 = blockIdx.x * 128;

    const int lr = tid >> 1;        // 0..127 tile row
    const int lc = (tid & 1) * 4;   // 0 or 4 (k offset)

    float acc[8][8];
    #pragma unroll
    for (int i = 0; i < 8; i++)
        #pragma unroll
        for (int j = 0; j < 8; j++) acc[i][j] = 0.f;

    const int arow = m0 + lr;
    const int brow = n0 + lr;
    const bool bvalid = (brow < N);

    for (int k0 = 0; k0 < K; k0 += 8) {
        float4 av = *(const float4*)(A + (size_t)arow * K + k0 + lc);
        float4 bv = make_float4(0.f, 0.f, 0.f, 0.f);
        if (bvalid) bv = *(const float4*)(B + (size_t)brow * K + k0 + lc);
        As[lc + 0][lr] = av.x; As[lc + 1][lr] = av.y;
        As[lc + 2][lr] = av.z; As[lc + 3][lr] = av.w;
        Bs[lc + 0][lr] = bv.x; Bs[lc + 1][lr] = bv.y;
        Bs[lc + 2][lr] = bv.z; Bs[lc + 3][lr] = bv.w;
        __syncthreads();

        #pragma unroll
        for (int kk = 0; kk < 8; kk++) {
            float4 a0 = *(float4*)&As[kk][ty * 8];
            float4 a1 = *(float4*)&As[kk][ty * 8 + 4];
            float4 b0 = *(float4*)&Bs[kk][tx * 8];
            float4 b1 = *(float4*)&Bs[kk][tx * 8 + 4];
            float am[8] = {a0.x, a0.y, a0.z, a0.w, a1.x, a1.y, a1.z, a1.w};
            float bn[8] = {b0.x, b0.y, b0.z, b0.w, b1.x, b1.y, b1.z, b1.w};
            #pragma unroll
            for (int i = 0; i < 8; i++)
                #pragma unroll
                for (int j = 0; j < 8; j++)
                    acc[i][j] += am[i] * bn[j];
        }
        __syncthreads();
    }

    #pragma unroll
    for (int i = 0; i < 8; i++) {
        const int m = m0 + ty * 8 + i;
        #pragma unroll
        for (int j = 0; j < 8; j++) {
            const int n = n0 + tx * 8 + j;
            if (n >= N) continue;
            float v = acc[i][j];
            if (MODE == 0) {
                C[(size_t)m * N + n] = v;
            } else if (MODE == 1) {
                // m = b*S + s ; n = h*DH + d  ->  [b*NH+h][s][d]
                const int b = m >> 10, s = m & 1023;
                const int h = n >> 6, d = n & 63;
                C[(((size_t)(b * NH + h)) * SEQ + s) * DH + d] = v;
            } else {
                C[(size_t)m * N + n] = v + bias[n];
            }
        }
    }
}

// ---------------------------------------------------------------------------
// Fused attention: one CTA per query index i. Rows = 64 (b,h) combos.
// score[r][j] = q[r] . (k[b(r),j] + rel[i,j])     (c2c + c2p fused)
// Online softmax over j tiles of 64; context accumulated in registers.
// ---------------------------------------------------------------------------
#define PIT 68   // smem pitch (floats): %4==0 for float4, avoids worst conflicts

#define SM_QT   (DH * PIT)             // sQt[d][r]
#define SM_KV   (4 * 64 * PIT)         // scores: [b][d][j] ; AV: [b][j][d]
#define SM_PT   (64 * PIT)             // sPt[j][r]
#define SM_TOTAL_FLOATS (SM_QT + SM_KV + SM_PT + 3 * 64)
#define SM_TOTAL_BYTES  (SM_TOTAL_FLOATS * 4)

__global__ __launch_bounds__(256)
void attn_kernel(const float* __restrict__ rel)
{
    extern __shared__ float sm[];
    float* sQt = sm;                   // [64][PIT]  (d-major: sQt[d*PIT + r])
    float* sKV = sQt + SM_QT;          // 4*64*PIT, dual-purpose
    float* sPt = sKV + SM_KV;          // [j][r]
    float* sM  = sPt + SM_PT;          // [64] running max
    float* sL  = sM + 64;              // [64] running sum
    float* sSc = sL + 64;              // [64] rescale factor

    const int i   = blockIdx.x;
    const int tid = threadIdx.x;
    const int tx  = tid & 15;
    const int ty  = tid >> 4;
    const int r0  = ty * 4;            // this thread's 4 rows
    const int bb  = r0 >> 4;           // batch of those rows (const within group)
    const int d0  = tx * 4;            // this thread's 4 context cols

    if (tid < 64) { sM[tid] = -INFINITY; sL[tid] = 0.f; }

    // Load Q for all 64 (b,h) rows at this i: sQt[d][r]
    #pragma unroll
    for (int t = 0; t < 16; t++) {
        const int idx = t * 256 + tid;
        const int r = idx >> 6, d = idx & 63;
        sQt[d * PIT + r] = g_q[((size_t)r * SEQ + i) * DH + d];
    }

    float cacc[4][4];
    #pragma unroll
    for (int a = 0; a < 4; a++)
        #pragma unroll
        for (int b = 0; b < 4; b++) cacc[a][b] = 0.f;

    __syncthreads();

    for (int j0 = 0; j0 < SEQ; j0 += 64) {
        // ---- load K+rel combined: sKV[b][d][j] ----
        #pragma unroll
        for (int t = 0; t < 16; t++) {
            const int idx = t * 256 + tid;
            const int j = idx >> 6, d = idx & 63;
            const float rl = rel[((size_t)i * SEQ + j0 + j) * DH + d];
            #pragma unroll
            for (int b = 0; b < 4; b++)
                sKV[(b * 64 + d) * PIT + j] =
                    g_k[((size_t)(b * SEQ + j0 + j)) * DH + d] + rl;
        }
        __syncthreads();

        // ---- scores: sacc[rr][jj] = sum_d Q[r0+rr][d]*KR[bb][j][d] ----
        float sacc[4][4];
        #pragma unroll
        for (int a = 0; a < 4; a++)
            #pragma unroll
            for (int b = 0; b < 4; b++) sacc[a][b] = 0.f;

        #pragma unroll 8
        for (int d = 0; d < 64; d++) {
            const float4 qa = *(float4*)&sQt[d * PIT + r0];
            const float4 kb = *(float4*)&sKV[(bb * 64 + d) * PIT + tx * 4];
            sacc[0][0] += qa.x * kb.x; sacc[0][1] += qa.x * kb.y;
            sacc[0][2] += qa.x * kb.z; sacc[0][3] += qa.x * kb.w;
            sacc[1][0] += qa.y * kb.x; sacc[1][1] += qa.y * kb.y;
            sacc[1][2] += qa.y * kb.z; sacc[1][3] += qa.y * kb.w;
            sacc[2][0] += qa.z * kb.x; sacc[2][1] += qa.z * kb.y;
            sacc[2][2] += qa.z * kb.z; sacc[2][3] += qa.z * kb.w;
            sacc[3][0] += qa.w * kb.x; sacc[3][1] += qa.w * kb.y;
            sacc[3][2] += qa.w * kb.z; sacc[3][3] += qa.w * kb.w;
        }
        // stash transposed for softmax + AV
        #pragma unroll
        for (int jj = 0; jj < 4; jj++)
            #pragma unroll
            for (int rr = 0; rr < 4; rr++)
                sPt[(tx * 4 + jj) * PIT + r0 + rr] = sacc[rr][jj];
        __syncthreads();

        // ---- online softmax update (one thread per row) ----
        if (tid < 64) {
            const int r = tid;
            const float mold = sM[r];
            float tmax = -INFINITY;
            #pragma unroll 8
            for (int j = 0; j < 64; j++)
                tmax = fmaxf(tmax, sPt[j * PIT + r]);
            const float mnew = fmaxf(mold, 0.125f * tmax);
            const float corr = __expf(mold - mnew);
            float ssum = 0.f;
            #pragma unroll 8
            for (int j = 0; j < 64; j++) {
                const float p = __expf(0.125f * sPt[j * PIT + r] - mnew);
                sPt[j * PIT + r] = p;
                ssum += p;
            }
            sL[r] = sL[r] * corr + ssum;
            sM[r] = mnew;
            sSc[r] = corr;
        }
        __syncthreads();

        // rescale running context by this tile's correction
        #pragma unroll
        for (int rr = 0; rr < 4; rr++) {
            const float c = sSc[r0 + rr];
            #pragma unroll
            for (int dd = 0; dd < 4; dd++) cacc[rr][dd] *= c;
        }

        // ---- load V into sKV (reuse): sKV[b][j][d] ----
        #pragma unroll
        for (int t = 0; t < 16; t++) {
            const int idx = t * 256 + tid;
            const int j = idx >> 6, d = idx & 63;
            #pragma unroll
            for (int b = 0; b < 4; b++)
                sKV[(b * 64 + j) * PIT + d] =
                    g_v[((size_t)(b * SEQ + j0 + j)) * DH + d];
        }
        __syncthreads();

        // ---- AV: cacc[rr][dd] += sum_j P[r][j]*V[b][j][d] ----
        #pragma unroll 8
        for (int j = 0; j < 64; j++) {
            const float4 pv = *(float4*)&sPt[j * PIT + r0];
            const float4 vv = *(float4*)&sKV[(bb * 64 + j) * PIT + d0];
            cacc[0][0] += pv.x * vv.x; cacc[0][1] += pv.x * vv.y;
            cacc[0][2] += pv.x * vv.z; cacc[0][3] += pv.x * vv.w;
            cacc[1][0] += pv.y * vv.x; cacc[1][1] += pv.y * vv.y;
            cacc[1][2] += pv.y * vv.z; cacc[1][3] += pv.y * vv.w;
            cacc[2][0] += pv.z * vv.x; cacc[2][1] += pv.z * vv.y;
            cacc[2][2] += pv.z * vv.z; cacc[2][3] += pv.z * vv.w;
            cacc[3][0] += pv.w * vv.x; cacc[3][1] += pv.w * vv.y;
            cacc[3][2] += pv.w * vv.z; cacc[3][3] += pv.w * vv.w;
        }
        __syncthreads();
    }

    // ---- normalize + write context: [b][i][h*DH + d] ----
    #pragma unroll
    for (int rr = 0; rr < 4; rr++) {
        const int r = r0 + rr;
        const float inv = 1.f / sL[r];
        const int b = r >> 4, h = r & 15;
        float4 o;
        o.x = cacc[rr][0] * inv; o.y = cacc[rr][1] * inv;
        o.z = cacc[rr][2] * inv; o.w = cacc[rr][3] * inv;
        *(float4*)&g_ctx[((size_t)(b * SEQ + i)) * DM + h * DH + d0] = o;
    }
}

// ---------------------------------------------------------------------------
extern "C" void kernel_launch(void* const* d_in, const int* in_sizes, int n_in,
                              void* d_out, int out_size)
{
    const float* x   = (const float*)d_in[0];
    const float* rel = (const float*)d_in[1];
    const float* Wq  = (const float*)d_in[2];
    const float* Wk  = (const float*)d_in[3];
    const float* Wv  = (const float*)d_in[4];
    const float* Wo  = (const float*)d_in[5];
    const float* bo  = (const float*)d_in[6];
    float* out = (float*)d_out;

    float *qb, *kb, *vb, *ctx;
    cudaGetSymbolAddress((void**)&qb,  g_q);
    cudaGetSymbolAddress((void**)&kb,  g_k);
    cudaGetSymbolAddress((void**)&vb,  g_v);
    cudaGetSymbolAddress((void**)&ctx, g_ctx);

    cudaFuncSetAttribute(attn_kernel,
                         cudaFuncAttributeMaxDynamicSharedMemorySize,
                         SM_TOTAL_BYTES);

    const int M = BATCH * SEQ;  // 4096

    // q = x @ Wq^T  -> [b,h,s,d]
    {
        dim3 grid(DM / 128, M / 128);
        gemm_tn<1><<<grid, 256>>>(x, Wq, nullptr, qb, M, DM, DM);
    }
    // k = x @ Wk^T , v = x @ Wv^T  -> [b*s, 64]
    {
        dim3 grid(1, M / 128);
        gemm_tn<0><<<grid, 256>>>(x, Wk, nullptr, kb, M, DH, DM);
        gemm_tn<0><<<grid, 256>>>(x, Wv, nullptr, vb, M, DH, DM);
    }
    // fused attention over all (b,h) for each query index i
    attn_kernel<<<SEQ, 256, SM_TOTAL_BYTES>>>(rel);

    // out = ctx @ Wo^T + bo
    {
        dim3 grid(DM / 128, M / 128);
        gemm_tn<2><<<grid, 256>>>(ctx, Wo, bo, out, M, DM, DM);
    }
}

// round 3
// speedup vs baseline: 1.7259x; 1.7259x over previous
#include <cuda_runtime.h>
#include <math.h>
#include <stdint.h>

#define BATCH 4
#define SEQ   1024
#define DM    1024
#define NH    16
#define DH    64

// Scratch (device globals — no allocation allowed)
__device__ float g_q[(size_t)BATCH*NH*SEQ*DH];   // [b*NH+h][s][d]
__device__ float g_k[(size_t)BATCH*SEQ*DH];      // [b*S+s][d]
__device__ float g_v[(size_t)BATCH*SEQ*DH];
__device__ float g_ctx[(size_t)BATCH*SEQ*DM];    // [b*S+s][h*DH+d]

// ---------------------------------------------------------------------------
// TF32 helpers
// ---------------------------------------------------------------------------
__device__ __forceinline__ float f2tf(float x) {
    uint32_t u;
    asm("cvt.rna.tf32.f32 %0, %1;" : "=r"(u) : "f"(x));
    return __uint_as_float(u);
}

__device__ __forceinline__ void mma_tf32(float* c, const uint32_t* a, const uint32_t* b) {
    asm volatile(
        "mma.sync.aligned.m16n8k8.row.col.f32.tf32.tf32.f32 "
        "{%0,%1,%2,%3}, {%4,%5,%6,%7}, {%8,%9}, {%0,%1,%2,%3};\n"
        : "+f"(c[0]), "+f"(c[1]), "+f"(c[2]), "+f"(c[3])
        : "r"(a[0]), "r"(a[1]), "r"(a[2]), "r"(a[3]), "r"(b[0]), "r"(b[1]));
}

// ---------------------------------------------------------------------------
// TF32 GEMM: C = A @ B^T (+bias). A[M,K] rm, B[N,K] rm.
// 128x128 tile, BK=16, 256 threads = 8 warps (4x2), warp tile 32x64.
// MODE 0: plain; MODE 1: q permuted write [b,h,s,d]; MODE 2: +bias
// ---------------------------------------------------------------------------
#define GP 20  // smem pitch: (20*g + t) % 32 distinct across a warp's frag lanes

template<int MODE>
__global__ __launch_bounds__(256)
void gemm_tf32(const float* __restrict__ A, const float* __restrict__ B,
               const float* __restrict__ bias, float* __restrict__ C,
               int M, int N, int K)
{
    __shared__ float sA[128 * GP];
    __shared__ float sB[128 * GP];

    const int tid  = threadIdx.x;
    const int lane = tid & 31;
    const int w    = tid >> 5;
    const int wr   = w >> 1;         // 0..3
    const int wc   = w & 1;          // 0..1
    const int g    = lane >> 2;      // 0..7
    const int t    = lane & 3;       // 0..3
    const int m0   = blockIdx.y * 128;
    const int n0   = blockIdx.x * 128;

    const int ldr = tid >> 2;        // 0..63
    const int ldc = (tid & 3) * 4;

    float acc[2][8][4];
    #pragma unroll
    for (int mt = 0; mt < 2; mt++)
        #pragma unroll
        for (int nt = 0; nt < 8; nt++)
            #pragma unroll
            for (int q = 0; q < 4; q++) acc[mt][nt][q] = 0.f;

    for (int k0 = 0; k0 < K; k0 += 16) {
        #pragma unroll
        for (int h = 0; h < 2; h++) {
            const int row = ldr + h * 64;
            float4 a4 = *(const float4*)&A[(size_t)(m0 + row) * K + k0 + ldc];
            float* da = &sA[row * GP + ldc];
            da[0] = f2tf(a4.x); da[1] = f2tf(a4.y); da[2] = f2tf(a4.z); da[3] = f2tf(a4.w);
            float4 b4 = make_float4(0.f, 0.f, 0.f, 0.f);
            if (n0 + row < N)
                b4 = *(const float4*)&B[(size_t)(n0 + row) * K + k0 + ldc];
            float* db = &sB[row * GP + ldc];
            db[0] = f2tf(b4.x); db[1] = f2tf(b4.y); db[2] = f2tf(b4.z); db[3] = f2tf(b4.w);
        }
        __syncthreads();

        #pragma unroll
        for (int ks = 0; ks < 2; ks++) {
            const int k = ks * 8;
            uint32_t af[2][4], bf[8][2];
            #pragma unroll
            for (int mt = 0; mt < 2; mt++) {
                const int mr = wr * 32 + mt * 16;
                af[mt][0] = __float_as_uint(sA[(mr + g) * GP + k + t]);
                af[mt][1] = __float_as_uint(sA[(mr + g + 8) * GP + k + t]);
                af[mt][2] = __float_as_uint(sA[(mr + g) * GP + k + t + 4]);
                af[mt][3] = __float_as_uint(sA[(mr + g + 8) * GP + k + t + 4]);
            }
            #pragma unroll
            for (int nt = 0; nt < 8; nt++) {
                const int nn = wc * 64 + nt * 8 + g;
                bf[nt][0] = __float_as_uint(sB[nn * GP + k + t]);
                bf[nt][1] = __float_as_uint(sB[nn * GP + k + t + 4]);
            }
            #pragma unroll
            for (int mt = 0; mt < 2; mt++)
                #pragma unroll
                for (int nt = 0; nt < 8; nt++)
                    mma_tf32(acc[mt][nt], af[mt], bf[nt]);
        }
        __syncthreads();
    }

    // epilogue
    #pragma unroll
    for (int mt = 0; mt < 2; mt++) {
        #pragma unroll
        for (int rr = 0; rr < 2; rr++) {
            const int m = m0 + wr * 32 + mt * 16 + g + rr * 8;
            #pragma unroll
            for (int nt = 0; nt < 8; nt++) {
                const int n = n0 + wc * 64 + nt * 8 + 2 * t;
                const float v0 = acc[mt][nt][rr * 2 + 0];
                const float v1 = acc[mt][nt][rr * 2 + 1];
                if (MODE == 0) {
                    if (n < N) *(float2*)&C[(size_t)m * N + n] = make_float2(v0, v1);
                } else if (MODE == 1) {
                    const int b = m >> 10, s = m & 1023;
                    const int h = n >> 6, d = n & 63;
                    *(float2*)&C[(((size_t)(b * NH + h)) * SEQ + s) * DH + d] =
                        make_float2(v0, v1);
                } else {
                    *(float2*)&C[(size_t)m * N + n] =
                        make_float2(v0 + bias[n], v1 + bias[n + 1]);
                }
            }
        }
    }
}

// ---------------------------------------------------------------------------
// Fused attention with TF32 MMA. One CTA per query index i.
// 64 (b,h) rows = 4 batches x 16 heads. j tiles of 64.
// scores = Q_b[16x64] @ (K_b + rel_i)[64x64]^T per batch (c2c+c2p fused)
// ---------------------------------------------------------------------------
#define AP 68  // attention smem pitch

#define SM_Q   (64 * AP)
#define SM_KR  (4 * 64 * AP)
#define SM_P   (64 * AP)
#define SM_ATTN_FLOATS (SM_Q + SM_KR + SM_P + 3 * 64)
#define SM_ATTN_BYTES  (SM_ATTN_FLOATS * 4)

__global__ __launch_bounds__(256, 2)
void attn_kernel(const float* __restrict__ rel,
                 const float* __restrict__ qb,
                 const float* __restrict__ kb,
                 const float* __restrict__ vb,
                 float* __restrict__ ctx)
{
    extern __shared__ float sm[];
    float* sQ  = sm;                 // [r=64][AP], tf32
    float* sKR = sQ + SM_Q;          // [b][j][d] for scores; aliased as sV [b][d][j]
    float* sP  = sKR + SM_KR;        // [r=64][AP]: scores, then tf32 probs
    float* sM  = sP + SM_P;          // [64]
    float* sL  = sM + 64;            // [64]
    float* sC  = sL + 64;            // [64] per-tile rescale

    const int i    = blockIdx.x;
    const int tid  = threadIdx.x;
    const int lane = tid & 31;
    const int w    = tid >> 5;
    const int b    = w >> 1;         // batch of this warp
    const int half = w & 1;          // n-half (j or d range)
    const int g    = lane >> 2;
    const int t    = lane & 3;

    if (tid < 64) { sM[tid] = -INFINITY; sL[tid] = 0.f; }

    // Load Q for all 64 rows at query i (tf32)
    #pragma unroll
    for (int tix = 0; tix < 16; tix++) {
        const int idx = tix * 256 + tid;
        const int r = idx >> 6, d = idx & 63;
        sQ[r * AP + d] = f2tf(qb[((size_t)r * SEQ + i) * DH + d]);
    }

    float cacc[4][4];
    #pragma unroll
    for (int a = 0; a < 4; a++)
        #pragma unroll
        for (int q = 0; q < 4; q++) cacc[a][q] = 0.f;

    for (int j0 = 0; j0 < SEQ; j0 += 64) {
        // ---- phase A: build KR[b][j][d] = tf32(K + rel) ----
        #pragma unroll
        for (int tix = 0; tix < 4; tix++) {
            const int idx = tix * 256 + tid;      // 1024 -> 64j x 16 d-quads
            const int j  = idx >> 4;
            const int d4 = (idx & 15) * 4;
            const float4 rv = *(const float4*)&rel[((size_t)i * SEQ + j0 + j) * DH + d4];
            #pragma unroll
            for (int bb = 0; bb < 4; bb++) {
                const float4 k4 = *(const float4*)&kb[((size_t)(bb * SEQ) + j0 + j) * DH + d4];
                float4 o;
                o.x = f2tf(k4.x + rv.x); o.y = f2tf(k4.y + rv.y);
                o.z = f2tf(k4.z + rv.z); o.w = f2tf(k4.w + rv.w);
                *(float4*)&sKR[(bb * 64 + j) * AP + d4] = o;
            }
        }
        __syncthreads();

        // ---- phase B: scores MMA (M=16 rows of batch b, N=32 j-cols) ----
        {
            float sf[4][4];
            #pragma unroll
            for (int nt = 0; nt < 4; nt++)
                #pragma unroll
                for (int q = 0; q < 4; q++) sf[nt][q] = 0.f;

            #pragma unroll
            for (int ks = 0; ks < 8; ks++) {
                const int k = ks * 8;
                uint32_t af[4], bf[2];
                af[0] = __float_as_uint(sQ[(b * 16 + g) * AP + k + t]);
                af[1] = __float_as_uint(sQ[(b * 16 + g + 8) * AP + k + t]);
                af[2] = __float_as_uint(sQ[(b * 16 + g) * AP + k + t + 4]);
                af[3] = __float_as_uint(sQ[(b * 16 + g + 8) * AP + k + t + 4]);
                #pragma unroll
                for (int nt = 0; nt < 4; nt++) {
                    const int n = half * 32 + nt * 8 + g;
                    bf[0] = __float_as_uint(sKR[(b * 64 + n) * AP + k + t]);
                    bf[1] = __float_as_uint(sKR[(b * 64 + n) * AP + k + t + 4]);
                    mma_tf32(sf[nt], af, bf);
                }
            }
            #pragma unroll
            for (int nt = 0; nt < 4; nt++) {
                const int jc = half * 32 + nt * 8 + 2 * t;
                *(float2*)&sP[(b * 16 + g) * AP + jc]     = make_float2(sf[nt][0], sf[nt][1]);
                *(float2*)&sP[(b * 16 + g + 8) * AP + jc] = make_float2(sf[nt][2], sf[nt][3]);
            }
        }
        __syncthreads();

        // ---- phase C: online softmax (4 threads/row) + V transpose store ----
        {
            const int r = tid >> 2, t4 = tid & 3;
            float* row = &sP[r * AP + t4 * 16];
            float lm = -INFINITY;
            #pragma unroll
            for (int jj = 0; jj < 16; jj++) lm = fmaxf(lm, row[jj]);
            lm = fmaxf(lm, __shfl_xor_sync(0xffffffffu, lm, 1));
            lm = fmaxf(lm, __shfl_xor_sync(0xffffffffu, lm, 2));
            const float mold = sM[r];
            const float mnew = fmaxf(mold, 0.125f * lm);
            const float corr = __expf(mold - mnew);
            float ls = 0.f;
            #pragma unroll
            for (int jj = 0; jj < 16; jj++) {
                const float p = __expf(0.125f * row[jj] - mnew);
                row[jj] = f2tf(p);
                ls += p;
            }
            ls += __shfl_xor_sync(0xffffffffu, ls, 1);
            ls += __shfl_xor_sync(0xffffffffu, ls, 2);
            if (t4 == 0) {
                sL[r] = sL[r] * corr + ls;
                sM[r] = mnew;
                sC[r] = corr;
            }
        }
        // V: [b][j][d] gmem -> sV[b][d][j] (tf32), reusing the KR buffer
        #pragma unroll
        for (int tix = 0; tix < 4; tix++) {
            const int idx = tix * 256 + tid;
            const int j  = idx >> 4;
            const int d4 = (idx & 15) * 4;
            #pragma unroll
            for (int bb = 0; bb < 4; bb++) {
                const float4 v4 = *(const float4*)&vb[((size_t)(bb * SEQ) + j0 + j) * DH + d4];
                sKR[(bb * 64 + d4 + 0) * AP + j] = f2tf(v4.x);
                sKR[(bb * 64 + d4 + 1) * AP + j] = f2tf(v4.y);
                sKR[(bb * 64 + d4 + 2) * AP + j] = f2tf(v4.z);
                sKR[(bb * 64 + d4 + 3) * AP + j] = f2tf(v4.w);
            }
        }
        __syncthreads();

        // ---- phase D: rescale ctx + AV MMA (N=32 d-cols, K=64 j) ----
        {
            const float c0 = sC[b * 16 + g];
            const float c1 = sC[b * 16 + g + 8];
            #pragma unroll
            for (int nt = 0; nt < 4; nt++) {
                cacc[nt][0] *= c0; cacc[nt][1] *= c0;
                cacc[nt][2] *= c1; cacc[nt][3] *= c1;
            }
            #pragma unroll
            for (int ks = 0; ks < 8; ks++) {
                const int k = ks * 8;   // j
                uint32_t af[4], bf[2];
                af[0] = __float_as_uint(sP[(b * 16 + g) * AP + k + t]);
                af[1] = __float_as_uint(sP[(b * 16 + g + 8) * AP + k + t]);
                af[2] = __float_as_uint(sP[(b * 16 + g) * AP + k + t + 4]);
                af[3] = __float_as_uint(sP[(b * 16 + g + 8) * AP + k + t + 4]);
                #pragma unroll
                for (int nt = 0; nt < 4; nt++) {
                    const int n = half * 32 + nt * 8 + g;   // d column
                    bf[0] = __float_as_uint(sKR[(b * 64 + n) * AP + k + t]);
                    bf[1] = __float_as_uint(sKR[(b * 64 + n) * AP + k + t + 4]);
                    mma_tf32(cacc[nt], af, bf);
                }
            }
        }
        __syncthreads();
    }

    // ---- epilogue: normalize + write ctx [b][i][h*DH + d] ----
    {
        const float inv0 = 1.f / sL[b * 16 + g];
        const float inv1 = 1.f / sL[b * 16 + g + 8];
        const size_t base = ((size_t)(b * SEQ) + i) * DM;
        #pragma unroll
        for (int nt = 0; nt < 4; nt++) {
            const int d = half * 32 + nt * 8 + 2 * t;
            *(float2*)&ctx[base + g * DH + d] =
                make_float2(cacc[nt][0] * inv0, cacc[nt][1] * inv0);
            *(float2*)&ctx[base + (g + 8) * DH + d] =
                make_float2(cacc[nt][2] * inv1, cacc[nt][3] * inv1);
        }
    }
}

// ---------------------------------------------------------------------------
extern "C" void kernel_launch(void* const* d_in, const int* in_sizes, int n_in,
                              void* d_out, int out_size)
{
    const float* x   = (const float*)d_in[0];
    const float* rel = (const float*)d_in[1];
    const float* Wq  = (const float*)d_in[2];
    const float* Wk  = (const float*)d_in[3];
    const float* Wv  = (const float*)d_in[4];
    const float* Wo  = (const float*)d_in[5];
    const float* bo  = (const float*)d_in[6];
    float* out = (float*)d_out;

    float *qb, *kb, *vb, *ctx;
    cudaGetSymbolAddress((void**)&qb,  g_q);
    cudaGetSymbolAddress((void**)&kb,  g_k);
    cudaGetSymbolAddress((void**)&vb,  g_v);
    cudaGetSymbolAddress((void**)&ctx, g_ctx);

    cudaFuncSetAttribute(attn_kernel,
                         cudaFuncAttributeMaxDynamicSharedMemorySize,
                         SM_ATTN_BYTES);

    const int M = BATCH * SEQ;  // 4096

    // q = x @ Wq^T -> [b,h,s,d]
    {
        dim3 grid(DM / 128, M / 128);
        gemm_tf32<1><<<grid, 256>>>(x, Wq, nullptr, qb, M, DM, DM);
    }
    // k, v = x @ Wk^T, x @ Wv^T -> [b*s, 64]
    {
        dim3 grid(1, M / 128);
        gemm_tf32<0><<<grid, 256>>>(x, Wk, nullptr, kb, M, DH, DM);
        gemm_tf32<0><<<grid, 256>>>(x, Wv, nullptr, vb, M, DH, DM);
    }
    // fused attention
    attn_kernel<<<SEQ, 256, SM_ATTN_BYTES>>>(rel, qb, kb, vb, ctx);

    // out = ctx @ Wo^T + bo
    {
        dim3 grid(DM / 128, M / 128);
        gemm_tf32<2><<<grid, 256>>>(ctx, Wo, bo, out, M, DM, DM);
    }
}

// round 5
// speedup vs baseline: 2.3630x; 1.3692x over previous
#include <cuda_runtime.h>
#include <math.h>
#include <stdint.h>

#define BATCH 4
#define SEQ   1024
#define DM    1024
#define NH    16
#define DH    64

// Scratch (device globals — no allocation allowed)
__device__ float g_q[(size_t)BATCH*NH*SEQ*DH];   // [b*NH+h][s][d]
__device__ float g_k[(size_t)BATCH*SEQ*DH];      // [b*S+s][d]
__device__ float g_v[(size_t)BATCH*SEQ*DH];
__device__ float g_ctx[(size_t)BATCH*SEQ*DM];    // [b*S+s][h*DH+d]

// ---------------------------------------------------------------------------
// TF32 helpers
// ---------------------------------------------------------------------------
__device__ __forceinline__ float f2tf(float x) {
    uint32_t u;
    asm("cvt.rna.tf32.f32 %0, %1;" : "=r"(u) : "f"(x));
    return __uint_as_float(u);
}

__device__ __forceinline__ void mma_tf32(float* c, const uint32_t* a, const uint32_t* b) {
    asm volatile(
        "mma.sync.aligned.m16n8k8.row.col.f32.tf32.tf32.f32 "
        "{%0,%1,%2,%3}, {%4,%5,%6,%7}, {%8,%9}, {%0,%1,%2,%3};\n"
        : "+f"(c[0]), "+f"(c[1]), "+f"(c[2]), "+f"(c[3])
        : "r"(a[0]), "r"(a[1]), "r"(a[2]), "r"(a[3]), "r"(b[0]), "r"(b[1]));
}

__device__ __forceinline__ void l2_prefetch(const void* p) {
    asm volatile("prefetch.global.L2 [%0];" :: "l"(p));
}

// ---------------------------------------------------------------------------
// TF32 GEMM: C = A @ B^T (+bias). A[M,K] rm, B[N,K] rm.
// 128x128 tile, BK=16, 256 threads = 8 warps (4x2), warp tile 32x64.
// Register double-buffered gmem pipeline.
// MODE 0: plain; MODE 1: q permuted write [b,h,s,d]; MODE 2: +bias
// ---------------------------------------------------------------------------
#define GP 20  // smem pitch: (20*g + t) % 32 distinct across a warp's frag lanes

template<int MODE>
__global__ __launch_bounds__(256, 2)
void gemm_tf32(const float* __restrict__ A, const float* __restrict__ B,
               const float* __restrict__ bias, float* __restrict__ C,
               int M, int N, int K)
{
    __shared__ float sA[128 * GP];
    __shared__ float sB[128 * GP];

    const int tid  = threadIdx.x;
    const int lane = tid & 31;
    const int w    = tid >> 5;
    const int wr   = w >> 1;         // 0..3
    const int wc   = w & 1;          // 0..1
    const int g    = lane >> 2;      // 0..7
    const int t    = lane & 3;       // 0..3
    const int m0   = blockIdx.y * 128;
    const int n0   = blockIdx.x * 128;

    const int ldr = tid >> 2;        // 0..63
    const int ldc = (tid & 3) * 4;

    float acc[2][8][4];
    #pragma unroll
    for (int mt = 0; mt < 2; mt++)
        #pragma unroll
        for (int nt = 0; nt < 8; nt++)
            #pragma unroll
            for (int q = 0; q < 4; q++) acc[mt][nt][q] = 0.f;

    float4 ar[2], br[2];
    // prologue loads (k0 = 0)
    #pragma unroll
    for (int h = 0; h < 2; h++) {
        const int row = ldr + h * 64;
        ar[h] = *(const float4*)&A[(size_t)(m0 + row) * K + ldc];
        br[h] = make_float4(0.f, 0.f, 0.f, 0.f);
        if (n0 + row < N)
            br[h] = *(const float4*)&B[(size_t)(n0 + row) * K + ldc];
    }

    for (int k0 = 0; k0 < K; k0 += 16) {
        // store staged registers to smem (with tf32 cvt)
        #pragma unroll
        for (int h = 0; h < 2; h++) {
            const int row = ldr + h * 64;
            float* da = &sA[row * GP + ldc];
            da[0] = f2tf(ar[h].x); da[1] = f2tf(ar[h].y);
            da[2] = f2tf(ar[h].z); da[3] = f2tf(ar[h].w);
            float* db = &sB[row * GP + ldc];
            db[0] = f2tf(br[h].x); db[1] = f2tf(br[h].y);
            db[2] = f2tf(br[h].z); db[3] = f2tf(br[h].w);
        }
        // prefetch next k slab into registers (overlaps with MMA below)
        if (k0 + 16 < K) {
            #pragma unroll
            for (int h = 0; h < 2; h++) {
                const int row = ldr + h * 64;
                ar[h] = *(const float4*)&A[(size_t)(m0 + row) * K + k0 + 16 + ldc];
                if (n0 + row < N)
                    br[h] = *(const float4*)&B[(size_t)(n0 + row) * K + k0 + 16 + ldc];
                else
                    br[h] = make_float4(0.f, 0.f, 0.f, 0.f);
            }
        }
        __syncthreads();

        #pragma unroll
        for (int ks = 0; ks < 2; ks++) {
            const int k = ks * 8;
            uint32_t af[2][4], bf[8][2];
            #pragma unroll
            for (int mt = 0; mt < 2; mt++) {
                const int mr = wr * 32 + mt * 16;
                af[mt][0] = __float_as_uint(sA[(mr + g) * GP + k + t]);
                af[mt][1] = __float_as_uint(sA[(mr + g + 8) * GP + k + t]);
                af[mt][2] = __float_as_uint(sA[(mr + g) * GP + k + t + 4]);
                af[mt][3] = __float_as_uint(sA[(mr + g + 8) * GP + k + t + 4]);
            }
            #pragma unroll
            for (int nt = 0; nt < 8; nt++) {
                const int nn = wc * 64 + nt * 8 + g;
                bf[nt][0] = __float_as_uint(sB[nn * GP + k + t]);
                bf[nt][1] = __float_as_uint(sB[nn * GP + k + t + 4]);
            }
            #pragma unroll
            for (int mt = 0; mt < 2; mt++)
                #pragma unroll
                for (int nt = 0; nt < 8; nt++)
                    mma_tf32(acc[mt][nt], af[mt], bf[nt]);
        }
        __syncthreads();
    }

    // epilogue
    #pragma unroll
    for (int mt = 0; mt < 2; mt++) {
        #pragma unroll
        for (int rr = 0; rr < 2; rr++) {
            const int m = m0 + wr * 32 + mt * 16 + g + rr * 8;
            #pragma unroll
            for (int nt = 0; nt < 8; nt++) {
                const int n = n0 + wc * 64 + nt * 8 + 2 * t;
                const float v0 = acc[mt][nt][rr * 2 + 0];
                const float v1 = acc[mt][nt][rr * 2 + 1];
                if (MODE == 0) {
                    if (n < N) *(float2*)&C[(size_t)m * N + n] = make_float2(v0, v1);
                } else if (MODE == 1) {
                    const int b = m >> 10, s = m & 1023;
                    const int h = n >> 6, d = n & 63;
                    *(float2*)&C[(((size_t)(b * NH + h)) * SEQ + s) * DH + d] =
                        make_float2(v0, v1);
                } else {
                    *(float2*)&C[(size_t)m * N + n] =
                        make_float2(v0 + bias[n], v1 + bias[n + 1]);
                }
            }
        }
    }
}

// ---------------------------------------------------------------------------
// Fused attention with TF32 MMA. One CTA per query index i.
// 64 (b,h) rows = 4 batches x 16 heads. j tiles of 64.
// scores = Q_b[16x64] @ (K_b + rel_i)[64x64]^T per batch (c2c+c2p fused)
// ---------------------------------------------------------------------------
#define AP 68  // attention smem pitch

#define SM_Q   (64 * AP)
#define SM_KR  (4 * 64 * AP)
#define SM_P   (64 * AP)
#define SM_ATTN_FLOATS (SM_Q + SM_KR + SM_P + 3 * 64)
#define SM_ATTN_BYTES  (SM_ATTN_FLOATS * 4)

__global__ __launch_bounds__(256, 2)
void attn_kernel(const float* __restrict__ rel,
                 const float* __restrict__ qb,
                 const float* __restrict__ kb,
                 const float* __restrict__ vb,
                 float* __restrict__ ctx)
{
    extern __shared__ float sm[];
    float* sQ  = sm;                 // [r=64][AP], tf32
    float* sKR = sQ + SM_Q;          // [b][j][d] for scores; aliased as sV [b][d][j]
    float* sP  = sKR + SM_KR;        // [r=64][AP]: scores, then tf32 probs
    float* sM  = sP + SM_P;          // [64]
    float* sL  = sM + 64;            // [64]
    float* sC  = sL + 64;            // [64] per-tile rescale

    const int i    = blockIdx.x;
    const int tid  = threadIdx.x;
    const int lane = tid & 31;
    const int w    = tid >> 5;
    const int b    = w >> 1;         // batch of this warp
    const int half = w & 1;          // n-half (j or d range)
    const int g    = lane >> 2;
    const int t    = lane & 3;

    if (tid < 64) { sM[tid] = -INFINITY; sL[tid] = 0.f; }

    // Load Q for all 64 rows at query i (tf32)
    #pragma unroll
    for (int tix = 0; tix < 16; tix++) {
        const int idx = tix * 256 + tid;
        const int r = idx >> 6, d = idx & 63;
        sQ[r * AP + d] = f2tf(qb[((size_t)r * SEQ + i) * DH + d]);
    }

    float cacc[4][4];
    #pragma unroll
    for (int a = 0; a < 4; a++)
        #pragma unroll
        for (int q = 0; q < 4; q++) cacc[a][q] = 0.f;

    for (int j0 = 0; j0 < SEQ; j0 += 64) {
        // ---- phase A: build KR[b][j][d] = tf32(K + rel) ----
        #pragma unroll
        for (int tix = 0; tix < 4; tix++) {
            const int idx = tix * 256 + tid;      // 1024 -> 64j x 16 d-quads
            const int j  = idx >> 4;
            const int d4 = (idx & 15) * 4;
            const float4 rv = *(const float4*)&rel[((size_t)i * SEQ + j0 + j) * DH + d4];
            // L2 prefetch next tile's rel (1 lane per 128B line)
            if (j0 + 64 < SEQ && (idx & 7) == 0)
                l2_prefetch(&rel[((size_t)i * SEQ + j0 + 64 + j) * DH + d4]);
            #pragma unroll
            for (int bb = 0; bb < 4; bb++) {
                const float4 k4 = *(const float4*)&kb[((size_t)(bb * SEQ) + j0 + j) * DH + d4];
                float4 o;
                o.x = f2tf(k4.x + rv.x); o.y = f2tf(k4.y + rv.y);
                o.z = f2tf(k4.z + rv.z); o.w = f2tf(k4.w + rv.w);
                *(float4*)&sKR[(bb * 64 + j) * AP + d4] = o;
            }
        }
        __syncthreads();

        // ---- phase B: scores MMA (M=16 rows of batch b, N=32 j-cols) ----
        {
            float sf[4][4];
            #pragma unroll
            for (int nt = 0; nt < 4; nt++)
                #pragma unroll
                for (int q = 0; q < 4; q++) sf[nt][q] = 0.f;

            #pragma unroll
            for (int ks = 0; ks < 8; ks++) {
                const int k = ks * 8;
                uint32_t af[4], bf[2];
                af[0] = __float_as_uint(sQ[(b * 16 + g) * AP + k + t]);
                af[1] = __float_as_uint(sQ[(b * 16 + g + 8) * AP + k + t]);
                af[2] = __float_as_uint(sQ[(b * 16 + g) * AP + k + t + 4]);
                af[3] = __float_as_uint(sQ[(b * 16 + g + 8) * AP + k + t + 4]);
                #pragma unroll
                for (int nt = 0; nt < 4; nt++) {
                    const int n = half * 32 + nt * 8 + g;
                    bf[0] = __float_as_uint(sKR[(b * 64 + n) * AP + k + t]);
                    bf[1] = __float_as_uint(sKR[(b * 64 + n) * AP + k + t + 4]);
                    mma_tf32(sf[nt], af, bf);
                }
            }
            #pragma unroll
            for (int nt = 0; nt < 4; nt++) {
                const int jc = half * 32 + nt * 8 + 2 * t;
                *(float2*)&sP[(b * 16 + g) * AP + jc]     = make_float2(sf[nt][0], sf[nt][1]);
                *(float2*)&sP[(b * 16 + g + 8) * AP + jc] = make_float2(sf[nt][2], sf[nt][3]);
            }
        }
        __syncthreads();

        // ---- phase C: online softmax (4 threads/row) + V transpose load ----
        {
            const int r = tid >> 2, t4 = tid & 3;
            float* row = &sP[r * AP + t4 * 16];
            float lm = -INFINITY;
            #pragma unroll
            for (int jj = 0; jj < 16; jj++) lm = fmaxf(lm, row[jj]);
            lm = fmaxf(lm, __shfl_xor_sync(0xffffffffu, lm, 1));
            lm = fmaxf(lm, __shfl_xor_sync(0xffffffffu, lm, 2));
            const float mold = sM[r];
            const float mnew = fmaxf(mold, 0.125f * lm);
            const float corr = __expf(mold - mnew);
            float ls = 0.f;
            #pragma unroll
            for (int jj = 0; jj < 16; jj++) {
                const float p = __expf(0.125f * row[jj] - mnew);
                row[jj] = f2tf(p);
                ls += p;
            }
            ls += __shfl_xor_sync(0xffffffffu, ls, 1);
            ls += __shfl_xor_sync(0xffffffffu, ls, 2);
            if (t4 == 0) {
                sL[r] = sL[r] * corr + ls;
                sM[r] = mnew;
                sC[r] = corr;
            }
        }
        // V: [b][j][d] gmem -> sV[b][d][j] (tf32), strided-d mapping:
        // lane owns (j, dbase), stores d = dbase + 16*s -> bank = 4*dbase + j
        // (16 banks x 2-way) instead of the old 8-way pattern.
        #pragma unroll
        for (int tix = 0; tix < 4; tix++) {
            const int idx = tix * 256 + tid;      // 1024 = 64 j x 16 dbase
            const int j  = idx >> 4;
            const int db = idx & 15;
            #pragma unroll
            for (int bb = 0; bb < 4; bb++) {
                const float* vrow = &vb[((size_t)(bb * SEQ) + j0 + j) * DH];
                #pragma unroll
                for (int s = 0; s < 4; s++) {
                    const int d = db + 16 * s;
                    sKR[(bb * 64 + d) * AP + j] = f2tf(vrow[d]);
                }
            }
        }
        __syncthreads();

        // ---- phase D: rescale ctx + AV MMA (N=32 d-cols, K=64 j) ----
        {
            const float c0 = sC[b * 16 + g];
            const float c1 = sC[b * 16 + g + 8];
            #pragma unroll
            for (int nt = 0; nt < 4; nt++) {
                cacc[nt][0] *= c0; cacc[nt][1] *= c0;
                cacc[nt][2] *= c1; cacc[nt][3] *= c1;
            }
            #pragma unroll
            for (int ks = 0; ks < 8; ks++) {
                const int k = ks * 8;   // j
                uint32_t af[4], bf[2];
                af[0] = __float_as_uint(sP[(b * 16 + g) * AP + k + t]);
                af[1] = __float_as_uint(sP[(b * 16 + g + 8) * AP + k + t]);
                af[2] = __float_as_uint(sP[(b * 16 + g) * AP + k + t + 4]);
                af[3] = __float_as_uint(sP[(b * 16 + g + 8) * AP + k + t + 4]);
                #pragma unroll
                for (int nt = 0; nt < 4; nt++) {
                    const int n = half * 32 + nt * 8 + g;   // d column
                    bf[0] = __float_as_uint(sKR[(b * 64 + n) * AP + k + t]);
                    bf[1] = __float_as_uint(sKR[(b * 64 + n) * AP + k + t + 4]);
                    mma_tf32(cacc[nt], af, bf);
                }
            }
        }
        __syncthreads();
    }

    // ---- epilogue: normalize + write ctx [b][i][h*DH + d] ----
    {
        const float inv0 = 1.f / sL[b * 16 + g];
        const float inv1 = 1.f / sL[b * 16 + g + 8];
        const size_t base = ((size_t)(b * SEQ) + i) * DM;
        #pragma unroll
        for (int nt = 0; nt < 4; nt++) {
            const int d = half * 32 + nt * 8 + 2 * t;
            *(float2*)&ctx[base + g * DH + d] =
                make_float2(cacc[nt][0] * inv0, cacc[nt][1] * inv0);
            *(float2*)&ctx[base + (g + 8) * DH + d] =
                make_float2(cacc[nt][2] * inv1, cacc[nt][3] * inv1);
        }
    }
}

// ---------------------------------------------------------------------------
extern "C" void kernel_launch(void* const* d_in, const int* in_sizes, int n_in,
                              void* d_out, int out_size)
{
    const float* x   = (const float*)d_in[0];
    const float* rel = (const float*)d_in[1];
    const float* Wq  = (const float*)d_in[2];
    const float* Wk  = (const float*)d_in[3];
    const float* Wv  = (const float*)d_in[4];
    const float* Wo  = (const float*)d_in[5];
    const float* bo  = (const float*)d_in[6];
    float* out = (float*)d_out;

    float *qb, *kb, *vb, *ctx;
    cudaGetSymbolAddress((void**)&qb,  g_q);
    cudaGetSymbolAddress((void**)&kb,  g_k);
    cudaGetSymbolAddress((void**)&vb,  g_v);
    cudaGetSymbolAddress((void**)&ctx, g_ctx);

    cudaFuncSetAttribute(attn_kernel,
                         cudaFuncAttributeMaxDynamicSharedMemorySize,
                         SM_ATTN_BYTES);

    const int M = BATCH * SEQ;  // 4096

    // q = x @ Wq^T -> [b,h,s,d]
    {
        dim3 grid(DM / 128, M / 128);
        gemm_tf32<1><<<grid, 256>>>(x, Wq, nullptr, qb, M, DM, DM);
    }
    // k, v = x @ Wk^T, x @ Wv^T -> [b*s, 64]
    {
        dim3 grid(1, M / 128);
        gemm_tf32<0><<<grid, 256>>>(x, Wk, nullptr, kb, M, DH, DM);
        gemm_tf32<0><<<grid, 256>>>(x, Wv, nullptr, vb, M, DH, DM);
    }
    // fused attention
    attn_kernel<<<SEQ, 256, SM_ATTN_BYTES>>>(rel, qb, kb, vb, ctx);

    // out = ctx @ Wo^T + bo
    {
        dim3 grid(DM / 128, M / 128);
        gemm_tf32<2><<<grid, 256>>>(ctx, Wo, bo, out, M, DM, DM);
    }
}